// round 12
// baseline (speedup 1.0000x reference)
#include <cuda_runtime.h>
#include <math.h>

#define NT 4
#define PT 8192
#define NH 32
#define NU 128
#define NPTS 32768

// ---------------- scratch (device globals; no allocations) ----------------
__device__ float g_KT[NT * NU * NU];
__device__ float g_QK[NT * NU * NU];           // q_w @ k_w^T
__device__ float g_VF[NT * NU * NU];           // v_w @ fc_w
__device__ float g_QKX[(size_t)NT * PT * NU];  // x @ QK
__device__ float g_HB[(size_t)NT * PT * NU];   // attn-weighted hist
__device__ float g_RAW[(size_t)NT * PT * NH];
__device__ float g_M[NT * NH];
__device__ float g_S[NT * NH];
__device__ int   g_cnt[NT * NPTS];             // counting-sort workspace
__device__ int   g_perm[NT * PT];              // entity order sorted by node idx

// ---------------- counting sort of entities by node index ----------------
__global__ void __launch_bounds__(1024) ksort_zero() {
    g_cnt[blockIdx.x * 1024 + threadIdx.x] = 0;
}
__global__ void __launch_bounds__(256) ksort_count(const int* __restrict__ eidx) {
    int t = blockIdx.y;
    int n = blockIdx.x * 256 + threadIdx.x;
    atomicAdd(&g_cnt[t * NPTS + eidx[t * PT + n]], 1);
}
__global__ void __launch_bounds__(1024) ksort_scan() {
    int t = blockIdx.x;
    int* cnt = g_cnt + t * NPTS;
    __shared__ int part[1024];
    int tid = threadIdx.x;
    int base = tid * 32;
    int local[32];
    int s = 0;
#pragma unroll
    for (int i = 0; i < 32; ++i) { local[i] = s; s += cnt[base + i]; }
    part[tid] = s;
    __syncthreads();
    for (int off = 1; off < 1024; off <<= 1) {
        int v = (tid >= off) ? part[tid - off] : 0;
        __syncthreads();
        part[tid] += v;
        __syncthreads();
    }
    int offset = (tid == 0) ? 0 : part[tid - 1];
#pragma unroll
    for (int i = 0; i < 32; ++i) cnt[base + i] = offset + local[i];
}
__global__ void __launch_bounds__(256) ksort_scatter(const int* __restrict__ eidx) {
    int t = blockIdx.y;
    int n = blockIdx.x * 256 + threadIdx.x;
    int pos = atomicAdd(&g_cnt[t * NPTS + eidx[t * PT + n]], 1);
    g_perm[t * PT + pos] = n;
}

// ---------------- prep ----------------
__global__ void __launch_bounds__(256) ktrans(const float* __restrict__ kw) {
    __shared__ float tile[32][33];
    int t = blockIdx.z;
    int bx = blockIdx.x * 32, by = blockIdx.y * 32;
    const float* src = kw + (size_t)t * NU * NU;
    float* dst = g_KT + (size_t)t * NU * NU;
    int tx = threadIdx.x, ty = threadIdx.y;
#pragma unroll
    for (int i = 0; i < 32; i += 8)
        tile[ty + i][tx] = src[(by + ty + i) * NU + bx + tx];
    __syncthreads();
#pragma unroll
    for (int i = 0; i < 32; i += 8)
        dst[(bx + ty + i) * NU + by + tx] = tile[tx][ty + i];
}

__global__ void __launch_bounds__(128) kqk(const float* __restrict__ qw) {
    int t = blockIdx.y, e = blockIdx.x, u = threadIdx.x;
    const float* q = qw + ((size_t)t * NU + e) * NU;
    const float* kt = g_KT + (size_t)t * NU * NU;
    float acc = 0.f;
#pragma unroll 8
    for (int v = 0; v < NU; ++v)
        acc = fmaf(q[v], kt[v * NU + u], acc);
    g_QK[((size_t)t * NU + e) * NU + u] = acc;
}

__global__ void __launch_bounds__(128) kvf(const float* __restrict__ vw,
                                           const float* __restrict__ fw) {
    int t = blockIdx.y, w = blockIdx.x, j = threadIdx.x;
    const float* vr = vw + ((size_t)t * NU + w) * NU;
    const float* f = fw + (size_t)t * NU * NU;
    float acc = 0.f;
#pragma unroll 8
    for (int u = 0; u < NU; ++u)
        acc = fmaf(vr[u], f[u * NU + j], acc);
    g_VF[((size_t)t * NU + w) * NU + j] = acc;
}

// ============ split-N gathered GEMM: QKX[t][n][64*half..] = X[eidx] @ QK[:, half] ============
__global__ void __launch_bounds__(256) kgemmH(const float* __restrict__ state,
                                              const int* __restrict__ eidx,
                                              int t, float* __restrict__ dst) {
    extern __shared__ float smem[];
    float* sX = smem;                        // [64][128] = 32KB
    float4* sW4 = (float4*)(smem + 64 * NU); // [128][16] float4 = 32KB
    int n0 = blockIdx.x * 64;
    int half = blockIdx.y;

    const float4* w4 = (const float4*)(g_QK + (size_t)t * NU * NU);
#pragma unroll
    for (int i = threadIdx.x; i < 2048; i += 256)
        sW4[i] = w4[(i >> 4) * 32 + half * 16 + (i & 15)];

    float4* sX4 = (float4*)sX;
#pragma unroll
    for (int i = threadIdx.x; i < 2048; i += 256) {
        int r = i >> 5, c = i & 31;
        int idx = eidx[t * PT + n0 + r];
        sX4[i] = __ldg((const float4*)(state + (size_t)idx * NU) + c);
    }
    __syncthreads();

    int tx = threadIdx.x & 15;
    int ty = threadIdx.x >> 4;
    float4 acc[4];
#pragma unroll
    for (int i = 0; i < 4; ++i) acc[i] = make_float4(0.f, 0.f, 0.f, 0.f);
#pragma unroll 4
    for (int v = 0; v < NU; ++v) {
        float4 b = sW4[v * 16 + tx];
#pragma unroll
        for (int i = 0; i < 4; ++i) {
            float a = sX[(ty * 4 + i) * NU + v];
            acc[i].x = fmaf(a, b.x, acc[i].x);
            acc[i].y = fmaf(a, b.y, acc[i].y);
            acc[i].z = fmaf(a, b.z, acc[i].z);
            acc[i].w = fmaf(a, b.w, acc[i].w);
        }
    }
#pragma unroll
    for (int i = 0; i < 4; ++i)
        ((float4*)(dst + ((size_t)t * PT + n0 + ty * 4 + i) * NU))[half * 16 + tx] = acc[i];
}

// ============ k1b(t): raw = hist . qkx — SORTED order, default loads (fill L2) ============
__global__ void __launch_bounds__(128) k1b(const float* __restrict__ hist,
                                           const int* __restrict__ eidx, int t) {
    int lane = threadIdx.x & 31;
    int warp = threadIdx.x >> 5;
    int n = g_perm[t * PT + blockIdx.x * 4 + warp];   // sorted by node idx
    int idx = eidx[t * PT + n];
    int g = lane >> 3;
    int c = lane & 7;

    const float4* qkrow = (const float4*)(g_QKX + ((size_t)t * PT + n) * NU);
    float4 qk[4];
#pragma unroll
    for (int j = 0; j < 4; ++j) qk[j] = __ldg(qkrow + j * 8 + c);

    const float* hb = hist + (size_t)idx * NH * NU;
    float* rawdst = g_RAW + ((size_t)t * PT + n) * NH;
#pragma unroll
    for (int i = 0; i < 8; ++i) {
        const float4* rowp = (const float4*)(hb + (4 * i + g) * NU);
        float4 v0 = __ldg(rowp + 0 * 8 + c);
        float4 v1 = __ldg(rowp + 1 * 8 + c);
        float4 v2 = __ldg(rowp + 2 * 8 + c);
        float4 v3 = __ldg(rowp + 3 * 8 + c);
        float p = 0.f;
        p = fmaf(v0.x, qk[0].x, p); p = fmaf(v0.y, qk[0].y, p);
        p = fmaf(v0.z, qk[0].z, p); p = fmaf(v0.w, qk[0].w, p);
        p = fmaf(v1.x, qk[1].x, p); p = fmaf(v1.y, qk[1].y, p);
        p = fmaf(v1.z, qk[1].z, p); p = fmaf(v1.w, qk[1].w, p);
        p = fmaf(v2.x, qk[2].x, p); p = fmaf(v2.y, qk[2].y, p);
        p = fmaf(v2.z, qk[2].z, p); p = fmaf(v2.w, qk[2].w, p);
        p = fmaf(v3.x, qk[3].x, p); p = fmaf(v3.y, qk[3].y, p);
        p = fmaf(v3.z, qk[3].z, p); p = fmaf(v3.w, qk[3].w, p);
        p += __shfl_xor_sync(0xffffffffu, p, 4);
        p += __shfl_xor_sync(0xffffffffu, p, 2);
        p += __shfl_xor_sync(0xffffffffu, p, 1);
        if (c == 0) rawdst[4 * i + g] = p;
    }
}

// ---------------- k2t(t): softmax stats for one type ----------------
__global__ void __launch_bounds__(256) k2t(int t) {
    int h = blockIdx.x;
    const float* base = g_RAW + (size_t)t * PT * NH + h;
    __shared__ float rm[256], rs[256];
    int tid = threadIdx.x;

    float m = -3.402823466e+38f, s = 0.f;
    for (int n = tid; n < PT; n += 256) {
        float x = base[(size_t)n * NH];
        if (x > m) { s = s * expf(m - x) + 1.f; m = x; }
        else s += expf(x - m);
    }
    rm[tid] = m; rs[tid] = s;
    __syncthreads();
#pragma unroll
    for (int st = 128; st; st >>= 1) {
        if (tid < st) {
            float m2 = rm[tid + st], s2 = rs[tid + st];
            float M = fmaxf(rm[tid], m2);
            rs[tid] = rs[tid] * expf(rm[tid] - M) + s2 * expf(m2 - M);
            rm[tid] = M;
        }
        __syncthreads();
    }
    if (tid == 0) { g_M[t * NH + h] = rm[0]; g_S[t * NH + h] = rs[0]; }
}

// ============ k3a(t): hbar = attn^T hist — SORTED order, evict-first (L2-warm) ============
__global__ void __launch_bounds__(128) k3a(const float* __restrict__ hist,
                                           const int* __restrict__ eidx, int t) {
    __shared__ float sw[4][NH];
    int lane = threadIdx.x & 31;
    int warp = threadIdx.x >> 5;
    int n = g_perm[t * PT + blockIdx.x * 4 + warp];   // same sorted order as k1b
    int idx = eidx[t * PT + n];

    {
        float r = g_RAW[((size_t)t * PT + n) * NH + lane];
        sw[warp][lane] = expf(r - g_M[t * NH + lane]) / g_S[t * NH + lane];
    }
    __syncwarp();

    const float4* h4 = (const float4*)(hist + (size_t)idx * NH * NU);
    float4 hb = make_float4(0.f, 0.f, 0.f, 0.f);
#pragma unroll 8
    for (int h = 0; h < NH; ++h) {
        float4 r4 = __ldcs(h4 + h * 32 + lane);
        float wh = sw[warp][h];
        hb.x = fmaf(wh, r4.x, hb.x); hb.y = fmaf(wh, r4.y, hb.y);
        hb.z = fmaf(wh, r4.z, hb.z); hb.w = fmaf(wh, r4.w, hb.w);
    }
    ((float4*)(g_HB + ((size_t)t * PT + n) * NU))[lane] = hb;
}

// ============ kout2H(t): out = relu(HB @ VF) + X @ qw  (two-phase fused, split-N) ============
__global__ void __launch_bounds__(256) kout2H(const float* __restrict__ state,
                                              const int* __restrict__ eidx,
                                              const float* __restrict__ qw,
                                              float* __restrict__ out, int t) {
    extern __shared__ float smem[];
    float* sX = smem;
    float4* sW4 = (float4*)(smem + 64 * NU);
    int n0 = blockIdx.x * 64;
    int half = blockIdx.y;
    int tx = threadIdx.x & 15;
    int ty = threadIdx.x >> 4;

    // ---- phase A: HB @ VF ----
    {
        const float4* w4 = (const float4*)(g_VF + (size_t)t * NU * NU);
#pragma unroll
        for (int i = threadIdx.x; i < 2048; i += 256)
            sW4[i] = w4[(i >> 4) * 32 + half * 16 + (i & 15)];
        const float4* x4 = (const float4*)(g_HB + ((size_t)t * PT + n0) * NU);
        float4* sX4 = (float4*)sX;
#pragma unroll
        for (int i = threadIdx.x; i < 2048; i += 256) sX4[i] = x4[i];
    }
    __syncthreads();

    float4 a1[4];
#pragma unroll
    for (int i = 0; i < 4; ++i) a1[i] = make_float4(0.f, 0.f, 0.f, 0.f);
#pragma unroll 4
    for (int v = 0; v < NU; ++v) {
        float4 b = sW4[v * 16 + tx];
#pragma unroll
        for (int i = 0; i < 4; ++i) {
            float a = sX[(ty * 4 + i) * NU + v];
            a1[i].x = fmaf(a, b.x, a1[i].x);
            a1[i].y = fmaf(a, b.y, a1[i].y);
            a1[i].z = fmaf(a, b.z, a1[i].z);
            a1[i].w = fmaf(a, b.w, a1[i].w);
        }
    }
    __syncthreads();

    // ---- phase B: gathered X @ qw ----
    {
        const float4* w4 = (const float4*)(qw + (size_t)t * NU * NU);
#pragma unroll
        for (int i = threadIdx.x; i < 2048; i += 256)
            sW4[i] = w4[(i >> 4) * 32 + half * 16 + (i & 15)];
        float4* sX4 = (float4*)sX;
#pragma unroll
        for (int i = threadIdx.x; i < 2048; i += 256) {
            int r = i >> 5, c = i & 31;
            int idx = eidx[t * PT + n0 + r];
            sX4[i] = __ldg((const float4*)(state + (size_t)idx * NU) + c);
        }
    }
    __syncthreads();

    float4 a2[4];
#pragma unroll
    for (int i = 0; i < 4; ++i) a2[i] = make_float4(0.f, 0.f, 0.f, 0.f);
#pragma unroll 4
    for (int v = 0; v < NU; ++v) {
        float4 b = sW4[v * 16 + tx];
#pragma unroll
        for (int i = 0; i < 4; ++i) {
            float a = sX[(ty * 4 + i) * NU + v];
            a2[i].x = fmaf(a, b.x, a2[i].x);
            a2[i].y = fmaf(a, b.y, a2[i].y);
            a2[i].z = fmaf(a, b.z, a2[i].z);
            a2[i].w = fmaf(a, b.w, a2[i].w);
        }
    }

#pragma unroll
    for (int i = 0; i < 4; ++i) {
        size_t row = (size_t)t * PT + n0 + ty * 4 + i;
        float4 r;
        r.x = fmaxf(a1[i].x, 0.f) + a2[i].x;
        r.y = fmaxf(a1[i].y, 0.f) + a2[i].y;
        r.z = fmaxf(a1[i].z, 0.f) + a2[i].z;
        r.w = fmaxf(a1[i].w, 0.f) + a2[i].w;
        ((float4*)(out + row * NU))[half * 16 + tx] = r;
    }
}

// ---------------- launch: sorted per-type L2-reuse pipeline ----------------
extern "C" void kernel_launch(void* const* d_in, const int* in_sizes, int n_in,
                              void* d_out, int out_size) {
    const float* state = (const float*)d_in[0];
    const float* hist  = (const float*)d_in[1];
    const int*   eidx  = (const int*)d_in[2];
    const float* qw    = (const float*)d_in[3];
    const float* kw    = (const float*)d_in[4];
    const float* vw    = (const float*)d_in[5];
    const float* fw    = (const float*)d_in[6];
    float* out = (float*)d_out;

    const int GSMEM = 64 * 1024;

    static bool init_done = false;
    static cudaStream_t s1, s2;
    static cudaEvent_t eP, gE[NT], hE[NT], e1, fE;
    static float* p_QKX;
    if (!init_done) {
        cudaFuncSetAttribute(kgemmH, cudaFuncAttributeMaxDynamicSharedMemorySize, GSMEM);
        cudaFuncSetAttribute(kout2H, cudaFuncAttributeMaxDynamicSharedMemorySize, GSMEM);
        int lo, hi;
        cudaDeviceGetStreamPriorityRange(&lo, &hi);
        cudaStreamCreateWithPriority(&s1, cudaStreamNonBlocking, hi);
        cudaStreamCreateWithPriority(&s2, cudaStreamNonBlocking, lo);
        cudaEventCreateWithFlags(&eP, cudaEventDisableTiming);
        for (int t = 0; t < NT; ++t) {
            cudaEventCreateWithFlags(&gE[t], cudaEventDisableTiming);
            cudaEventCreateWithFlags(&hE[t], cudaEventDisableTiming);
        }
        cudaEventCreateWithFlags(&e1, cudaEventDisableTiming);
        cudaEventCreateWithFlags(&fE, cudaEventDisableTiming);
        cudaGetSymbolAddress((void**)&p_QKX, g_QKX);
        init_done = true;
    }

    // ---- s0: counting sort (per type), prep, per-type QKX GEMMs ----
    ksort_zero<<<NT * NPTS / 1024, 1024>>>();
    ksort_count<<<dim3(PT / 256, NT), 256>>>(eidx);
    ktrans<<<dim3(4, 4, NT), dim3(32, 8)>>>(kw);    // independent, fills gap
    ksort_scan<<<NT, 1024>>>();
    ksort_scatter<<<dim3(PT / 256, NT), 256>>>(eidx);
    kqk<<<dim3(NU, NT), NU>>>(qw);
    cudaEventRecord(eP, 0);
    for (int t = 0; t < NT; ++t) {
        kgemmH<<<dim3(PT / 64, 2), 256, GSMEM>>>(state, eidx, t, p_QKX);
        cudaEventRecord(gE[t], 0);
    }

    // ---- s1 (high prio): per-type chain k1b -> k2t -> k3a (sorted order) ----
    for (int t = 0; t < NT; ++t) {
        cudaStreamWaitEvent(s1, gE[t], 0);
        k1b<<<PT / 4, 128, 0, s1>>>(hist, eidx, t);
        k2t<<<NH, 256, 0, s1>>>(t);
        k3a<<<PT / 4, 128, 0, s1>>>(hist, eidx, t);
        cudaEventRecord(hE[t], s1);
    }
    cudaEventRecord(e1, s1);

    // ---- s2 (low prio): kvf hidden; fused epilogue per type ----
    cudaStreamWaitEvent(s2, eP, 0);
    kvf<<<dim3(NU, NT), NU, 0, s2>>>(vw, fw);
    for (int t = 0; t < NT; ++t) {
        cudaStreamWaitEvent(s2, hE[t], 0);
        kout2H<<<dim3(PT / 64, 2), 256, GSMEM, s2>>>(state, eidx, qw, out, t);
    }
    cudaEventRecord(fE, s2);

    // ---- join ----
    cudaStreamWaitEvent(0, e1, 0);
    cudaStreamWaitEvent(0, fE, 0);
}

// round 13
// speedup vs baseline: 1.4115x; 1.4115x over previous
#include <cuda_runtime.h>
#include <math.h>

#define NT 4
#define PT 8192
#define NH 32
#define NU 128

// ---------------- scratch (device globals; no allocations) ----------------
__device__ float g_KT[NT * NU * NU];
__device__ float g_QK[NT * NU * NU];           // q_w @ k_w^T
__device__ float g_VF[NT * NU * NU];           // v_w @ fc_w
__device__ float g_QKX[(size_t)NT * PT * NU];  // x @ QK
__device__ float g_HB[(size_t)NT * PT * NU];   // attn-weighted hist
__device__ float g_RAW[(size_t)NT * PT * NH];
__device__ float g_M[NT * NH];
__device__ float g_S[NT * NH];

// ---------------- prep ----------------
__global__ void __launch_bounds__(256) ktrans(const float* __restrict__ kw) {
    __shared__ float tile[32][33];
    int t = blockIdx.z;
    int bx = blockIdx.x * 32, by = blockIdx.y * 32;
    const float* src = kw + (size_t)t * NU * NU;
    float* dst = g_KT + (size_t)t * NU * NU;
    int tx = threadIdx.x, ty = threadIdx.y;
#pragma unroll
    for (int i = 0; i < 32; i += 8)
        tile[ty + i][tx] = src[(by + ty + i) * NU + bx + tx];
    __syncthreads();
#pragma unroll
    for (int i = 0; i < 32; i += 8)
        dst[(bx + ty + i) * NU + by + tx] = tile[tx][ty + i];
}

__global__ void __launch_bounds__(128) kqk(const float* __restrict__ qw) {
    int t = blockIdx.y, e = blockIdx.x, u = threadIdx.x;
    const float* q = qw + ((size_t)t * NU + e) * NU;
    const float* kt = g_KT + (size_t)t * NU * NU;
    float acc = 0.f;
#pragma unroll 8
    for (int v = 0; v < NU; ++v)
        acc = fmaf(q[v], kt[v * NU + u], acc);
    g_QK[((size_t)t * NU + e) * NU + u] = acc;
}

__global__ void __launch_bounds__(128) kvf(const float* __restrict__ vw,
                                           const float* __restrict__ fw) {
    int t = blockIdx.y, w = blockIdx.x, j = threadIdx.x;
    const float* vr = vw + ((size_t)t * NU + w) * NU;
    const float* f = fw + (size_t)t * NU * NU;
    float acc = 0.f;
#pragma unroll 8
    for (int u = 0; u < NU; ++u)
        acc = fmaf(vr[u], f[u * NU + j], acc);
    g_VF[((size_t)t * NU + w) * NU + j] = acc;
}

// ============ split-N gathered GEMM: QKX[t][n][64*half..] = X[eidx] @ QK[:, half] ============
__global__ void __launch_bounds__(256) kgemmH(const float* __restrict__ state,
                                              const int* __restrict__ eidx,
                                              int t, float* __restrict__ dst) {
    extern __shared__ float smem[];
    float* sX = smem;                        // [64][128] = 32KB
    float4* sW4 = (float4*)(smem + 64 * NU); // [128][16] float4 = 32KB
    int n0 = blockIdx.x * 64;
    int half = blockIdx.y;

    const float4* w4 = (const float4*)(g_QK + (size_t)t * NU * NU);
#pragma unroll
    for (int i = threadIdx.x; i < 2048; i += 256)
        sW4[i] = w4[(i >> 4) * 32 + half * 16 + (i & 15)];

    float4* sX4 = (float4*)sX;
#pragma unroll
    for (int i = threadIdx.x; i < 2048; i += 256) {
        int r = i >> 5, c = i & 31;
        int idx = eidx[t * PT + n0 + r];
        sX4[i] = __ldg((const float4*)(state + (size_t)idx * NU) + c);
    }
    __syncthreads();

    int tx = threadIdx.x & 15;
    int ty = threadIdx.x >> 4;
    float4 acc[4];
#pragma unroll
    for (int i = 0; i < 4; ++i) acc[i] = make_float4(0.f, 0.f, 0.f, 0.f);
#pragma unroll 4
    for (int v = 0; v < NU; ++v) {
        float4 b = sW4[v * 16 + tx];
#pragma unroll
        for (int i = 0; i < 4; ++i) {
            float a = sX[(ty * 4 + i) * NU + v];
            acc[i].x = fmaf(a, b.x, acc[i].x);
            acc[i].y = fmaf(a, b.y, acc[i].y);
            acc[i].z = fmaf(a, b.z, acc[i].z);
            acc[i].w = fmaf(a, b.w, acc[i].w);
        }
    }
#pragma unroll
    for (int i = 0; i < 4; ++i)
        ((float4*)(dst + ((size_t)t * PT + n0 + ty * 4 + i) * NU))[half * 16 + tx] = acc[i];
}

// ============ k1b(t): raw = hist . qkx — quarter-warp rows, evict-first stream ============
__global__ void __launch_bounds__(128) k1b(const float* __restrict__ hist,
                                           const int* __restrict__ eidx, int t) {
    int lane = threadIdx.x & 31;
    int warp = threadIdx.x >> 5;
    int n = blockIdx.x * 4 + warp;
    int idx = eidx[t * PT + n];
    int g = lane >> 3;
    int c = lane & 7;

    const float4* qkrow = (const float4*)(g_QKX + ((size_t)t * PT + n) * NU);
    float4 qk[4];
#pragma unroll
    for (int j = 0; j < 4; ++j) qk[j] = __ldg(qkrow + j * 8 + c);

    const float* hb = hist + (size_t)idx * NH * NU;
    float* rawdst = g_RAW + ((size_t)t * PT + n) * NH;
#pragma unroll
    for (int i = 0; i < 8; ++i) {
        const float4* rowp = (const float4*)(hb + (4 * i + g) * NU);
        float4 v0 = __ldcs(rowp + 0 * 8 + c);
        float4 v1 = __ldcs(rowp + 1 * 8 + c);
        float4 v2 = __ldcs(rowp + 2 * 8 + c);
        float4 v3 = __ldcs(rowp + 3 * 8 + c);
        float p = 0.f;
        p = fmaf(v0.x, qk[0].x, p); p = fmaf(v0.y, qk[0].y, p);
        p = fmaf(v0.z, qk[0].z, p); p = fmaf(v0.w, qk[0].w, p);
        p = fmaf(v1.x, qk[1].x, p); p = fmaf(v1.y, qk[1].y, p);
        p = fmaf(v1.z, qk[1].z, p); p = fmaf(v1.w, qk[1].w, p);
        p = fmaf(v2.x, qk[2].x, p); p = fmaf(v2.y, qk[2].y, p);
        p = fmaf(v2.z, qk[2].z, p); p = fmaf(v2.w, qk[2].w, p);
        p = fmaf(v3.x, qk[3].x, p); p = fmaf(v3.y, qk[3].y, p);
        p = fmaf(v3.z, qk[3].z, p); p = fmaf(v3.w, qk[3].w, p);
        p += __shfl_xor_sync(0xffffffffu, p, 4);
        p += __shfl_xor_sync(0xffffffffu, p, 2);
        p += __shfl_xor_sync(0xffffffffu, p, 1);
        if (c == 0) rawdst[4 * i + g] = p;
    }
}

// ---------------- k2t(t): softmax stats for one type ----------------
__global__ void __launch_bounds__(256) k2t(int t) {
    int h = blockIdx.x;
    const float* base = g_RAW + (size_t)t * PT * NH + h;
    __shared__ float rm[256], rs[256];
    int tid = threadIdx.x;

    float m = -3.402823466e+38f, s = 0.f;
    for (int n = tid; n < PT; n += 256) {
        float x = base[(size_t)n * NH];
        if (x > m) { s = s * expf(m - x) + 1.f; m = x; }
        else s += expf(x - m);
    }
    rm[tid] = m; rs[tid] = s;
    __syncthreads();
#pragma unroll
    for (int st = 128; st; st >>= 1) {
        if (tid < st) {
            float m2 = rm[tid + st], s2 = rs[tid + st];
            float M = fmaxf(rm[tid], m2);
            rs[tid] = rs[tid] * expf(rm[tid] - M) + s2 * expf(m2 - M);
            rm[tid] = M;
        }
        __syncthreads();
    }
    if (tid == 0) { g_M[t * NH + h] = rm[0]; g_S[t * NH + h] = rs[0]; }
}

// ============ k3a(t): hbar = attn^T hist — SPARSE: skip rows with weight == 0.0f ============
// Bit-exact: fp32 softmax weights underflow to exactly 0.0 for all but the near-argmax
// entities per (t,h) (score gaps are ~hundreds; expf underflows below -87). The fp32
// reference underflows identically, and fmaf(0, finite, acc) == acc, so skipping is exact.
__global__ void __launch_bounds__(128) k3a(const float* __restrict__ hist,
                                           const int* __restrict__ eidx, int t) {
    int lane = threadIdx.x & 31;
    int warp = threadIdx.x >> 5;
    int n = blockIdx.x * 4 + warp;
    int idx = eidx[t * PT + n];

    float r = g_RAW[((size_t)t * PT + n) * NH + lane];
    float wv = expf(r - g_M[t * NH + lane]) / g_S[t * NH + lane];
    unsigned mask = __ballot_sync(0xffffffffu, wv != 0.0f);

    float4 hb = make_float4(0.f, 0.f, 0.f, 0.f);
    const float4* h4 = (const float4*)(hist + (size_t)idx * NH * NU);
    while (mask) {
        int h = __ffs(mask) - 1;
        mask &= mask - 1;
        float wh = __shfl_sync(0xffffffffu, wv, h);
        float4 r4 = __ldg(h4 + h * 32 + lane);
        hb.x = fmaf(wh, r4.x, hb.x); hb.y = fmaf(wh, r4.y, hb.y);
        hb.z = fmaf(wh, r4.z, hb.z); hb.w = fmaf(wh, r4.w, hb.w);
    }
    ((float4*)(g_HB + ((size_t)t * PT + n) * NU))[lane] = hb;
}

// ============ kout2H(t): out = relu(HB @ VF) + X @ qw  (two-phase fused, split-N) ============
__global__ void __launch_bounds__(256) kout2H(const float* __restrict__ state,
                                              const int* __restrict__ eidx,
                                              const float* __restrict__ qw,
                                              float* __restrict__ out, int t) {
    extern __shared__ float smem[];
    float* sX = smem;
    float4* sW4 = (float4*)(smem + 64 * NU);
    int n0 = blockIdx.x * 64;
    int half = blockIdx.y;
    int tx = threadIdx.x & 15;
    int ty = threadIdx.x >> 4;

    // ---- phase A: HB @ VF ----
    {
        const float4* w4 = (const float4*)(g_VF + (size_t)t * NU * NU);
#pragma unroll
        for (int i = threadIdx.x; i < 2048; i += 256)
            sW4[i] = w4[(i >> 4) * 32 + half * 16 + (i & 15)];
        const float4* x4 = (const float4*)(g_HB + ((size_t)t * PT + n0) * NU);
        float4* sX4 = (float4*)sX;
#pragma unroll
        for (int i = threadIdx.x; i < 2048; i += 256) sX4[i] = x4[i];
    }
    __syncthreads();

    float4 a1[4];
#pragma unroll
    for (int i = 0; i < 4; ++i) a1[i] = make_float4(0.f, 0.f, 0.f, 0.f);
#pragma unroll 4
    for (int v = 0; v < NU; ++v) {
        float4 b = sW4[v * 16 + tx];
#pragma unroll
        for (int i = 0; i < 4; ++i) {
            float a = sX[(ty * 4 + i) * NU + v];
            a1[i].x = fmaf(a, b.x, a1[i].x);
            a1[i].y = fmaf(a, b.y, a1[i].y);
            a1[i].z = fmaf(a, b.z, a1[i].z);
            a1[i].w = fmaf(a, b.w, a1[i].w);
        }
    }
    __syncthreads();

    // ---- phase B: gathered X @ qw ----
    {
        const float4* w4 = (const float4*)(qw + (size_t)t * NU * NU);
#pragma unroll
        for (int i = threadIdx.x; i < 2048; i += 256)
            sW4[i] = w4[(i >> 4) * 32 + half * 16 + (i & 15)];
        float4* sX4 = (float4*)sX;
#pragma unroll
        for (int i = threadIdx.x; i < 2048; i += 256) {
            int r = i >> 5, c = i & 31;
            int idx = eidx[t * PT + n0 + r];
            sX4[i] = __ldg((const float4*)(state + (size_t)idx * NU) + c);
        }
    }
    __syncthreads();

    float4 a2[4];
#pragma unroll
    for (int i = 0; i < 4; ++i) a2[i] = make_float4(0.f, 0.f, 0.f, 0.f);
#pragma unroll 4
    for (int v = 0; v < NU; ++v) {
        float4 b = sW4[v * 16 + tx];
#pragma unroll
        for (int i = 0; i < 4; ++i) {
            float a = sX[(ty * 4 + i) * NU + v];
            a2[i].x = fmaf(a, b.x, a2[i].x);
            a2[i].y = fmaf(a, b.y, a2[i].y);
            a2[i].z = fmaf(a, b.z, a2[i].z);
            a2[i].w = fmaf(a, b.w, a2[i].w);
        }
    }

#pragma unroll
    for (int i = 0; i < 4; ++i) {
        size_t row = (size_t)t * PT + n0 + ty * 4 + i;
        float4 r;
        r.x = fmaxf(a1[i].x, 0.f) + a2[i].x;
        r.y = fmaxf(a1[i].y, 0.f) + a2[i].y;
        r.z = fmaxf(a1[i].z, 0.f) + a2[i].z;
        r.w = fmaxf(a1[i].w, 0.f) + a2[i].w;
        ((float4*)(out + row * NU))[half * 16 + tx] = r;
    }
}

// ---------------- launch: per-type pipeline with sparse pass 2 ----------------
extern "C" void kernel_launch(void* const* d_in, const int* in_sizes, int n_in,
                              void* d_out, int out_size) {
    const float* state = (const float*)d_in[0];
    const float* hist  = (const float*)d_in[1];
    const int*   eidx  = (const int*)d_in[2];
    const float* qw    = (const float*)d_in[3];
    const float* kw    = (const float*)d_in[4];
    const float* vw    = (const float*)d_in[5];
    const float* fw    = (const float*)d_in[6];
    float* out = (float*)d_out;

    const int GSMEM = 64 * 1024;

    static bool init_done = false;
    static cudaStream_t s1, s2;
    static cudaEvent_t eP, gE[NT], hE[NT], e1, fE;
    static float* p_QKX;
    if (!init_done) {
        cudaFuncSetAttribute(kgemmH, cudaFuncAttributeMaxDynamicSharedMemorySize, GSMEM);
        cudaFuncSetAttribute(kout2H, cudaFuncAttributeMaxDynamicSharedMemorySize, GSMEM);
        int lo, hi;
        cudaDeviceGetStreamPriorityRange(&lo, &hi);
        cudaStreamCreateWithPriority(&s1, cudaStreamNonBlocking, hi);
        cudaStreamCreateWithPriority(&s2, cudaStreamNonBlocking, lo);
        cudaEventCreateWithFlags(&eP, cudaEventDisableTiming);
        for (int t = 0; t < NT; ++t) {
            cudaEventCreateWithFlags(&gE[t], cudaEventDisableTiming);
            cudaEventCreateWithFlags(&hE[t], cudaEventDisableTiming);
        }
        cudaEventCreateWithFlags(&e1, cudaEventDisableTiming);
        cudaEventCreateWithFlags(&fE, cudaEventDisableTiming);
        cudaGetSymbolAddress((void**)&p_QKX, g_QKX);
        init_done = true;
    }

    // ---- s0: prep + per-type QKX GEMMs ----
    ktrans<<<dim3(4, 4, NT), dim3(32, 8)>>>(kw);
    kqk<<<dim3(NU, NT), NU>>>(qw);
    cudaEventRecord(eP, 0);
    for (int t = 0; t < NT; ++t) {
        kgemmH<<<dim3(PT / 64, 2), 256, GSMEM>>>(state, eidx, t, p_QKX);
        cudaEventRecord(gE[t], 0);
    }

    // ---- s1 (high prio): per-type chain k1b -> k2t -> k3a(sparse) ----
    for (int t = 0; t < NT; ++t) {
        cudaStreamWaitEvent(s1, gE[t], 0);
        k1b<<<PT / 4, 128, 0, s1>>>(hist, eidx, t);
        k2t<<<NH, 256, 0, s1>>>(t);
        k3a<<<PT / 4, 128, 0, s1>>>(hist, eidx, t);
        cudaEventRecord(hE[t], s1);
    }
    cudaEventRecord(e1, s1);

    // ---- s2 (low prio): kvf hidden; fused epilogue per type ----
    cudaStreamWaitEvent(s2, eP, 0);
    kvf<<<dim3(NU, NT), NU, 0, s2>>>(vw, fw);
    for (int t = 0; t < NT; ++t) {
        cudaStreamWaitEvent(s2, hE[t], 0);
        kout2H<<<dim3(PT / 64, 2), 256, GSMEM, s2>>>(state, eidx, qw, out, t);
    }
    cudaEventRecord(fE, s2);

    // ---- join ----
    cudaStreamWaitEvent(0, e1, 0);
    cudaStreamWaitEvent(0, fE, 0);
}

// round 14
// speedup vs baseline: 1.5189x; 1.0761x over previous
#include <cuda_runtime.h>
#include <math.h>

#define NT 4
#define PT 8192
#define NH 32
#define NU 128

// ---------------- scratch (device globals; no allocations) ----------------
__device__ float g_KT[NT * NU * NU];
__device__ float g_QK[NT * NU * NU];           // q_w @ k_w^T
__device__ float g_VF[NT * NU * NU];           // v_w @ fc_w
__device__ float g_QKX[(size_t)NT * PT * NU];  // x @ QK
__device__ float g_RAW[(size_t)NT * PT * NH];
__device__ float g_M[NT * NH];
__device__ float g_S[NT * NH];

// ---------------- prep ----------------
__global__ void __launch_bounds__(256) ktrans(const float* __restrict__ kw) {
    __shared__ float tile[32][33];
    int t = blockIdx.z;
    int bx = blockIdx.x * 32, by = blockIdx.y * 32;
    const float* src = kw + (size_t)t * NU * NU;
    float* dst = g_KT + (size_t)t * NU * NU;
    int tx = threadIdx.x, ty = threadIdx.y;
#pragma unroll
    for (int i = 0; i < 32; i += 8)
        tile[ty + i][tx] = src[(by + ty + i) * NU + bx + tx];
    __syncthreads();
#pragma unroll
    for (int i = 0; i < 32; i += 8)
        dst[(bx + ty + i) * NU + by + tx] = tile[tx][ty + i];
}

__global__ void __launch_bounds__(128) kqk(const float* __restrict__ qw) {
    int t = blockIdx.y, e = blockIdx.x, u = threadIdx.x;
    const float* q = qw + ((size_t)t * NU + e) * NU;
    const float* kt = g_KT + (size_t)t * NU * NU;
    float acc = 0.f;
#pragma unroll 8
    for (int v = 0; v < NU; ++v)
        acc = fmaf(q[v], kt[v * NU + u], acc);
    g_QK[((size_t)t * NU + e) * NU + u] = acc;
}

__global__ void __launch_bounds__(128) kvf(const float* __restrict__ vw,
                                           const float* __restrict__ fw) {
    int t = blockIdx.y, w = blockIdx.x, j = threadIdx.x;
    const float* vr = vw + ((size_t)t * NU + w) * NU;
    const float* f = fw + (size_t)t * NU * NU;
    float acc = 0.f;
#pragma unroll 8
    for (int u = 0; u < NU; ++u)
        acc = fmaf(vr[u], f[u * NU + j], acc);
    g_VF[((size_t)t * NU + w) * NU + j] = acc;
}

// ============ split-N gathered GEMM: QKX[t][n][64*half..] = X[eidx] @ QK[:, half] ============
__global__ void __launch_bounds__(256) kgemmH(const float* __restrict__ state,
                                              const int* __restrict__ eidx,
                                              int t, float* __restrict__ dst) {
    extern __shared__ float smem[];
    float* sX = smem;                        // [64][128] = 32KB
    float4* sW4 = (float4*)(smem + 64 * NU); // [128][16] float4 = 32KB
    int n0 = blockIdx.x * 64;
    int half = blockIdx.y;

    const float4* w4 = (const float4*)(g_QK + (size_t)t * NU * NU);
#pragma unroll
    for (int i = threadIdx.x; i < 2048; i += 256)
        sW4[i] = w4[(i >> 4) * 32 + half * 16 + (i & 15)];

    float4* sX4 = (float4*)sX;
#pragma unroll
    for (int i = threadIdx.x; i < 2048; i += 256) {
        int r = i >> 5, c = i & 31;
        int idx = eidx[t * PT + n0 + r];
        sX4[i] = __ldg((const float4*)(state + (size_t)idx * NU) + c);
    }
    __syncthreads();

    int tx = threadIdx.x & 15;
    int ty = threadIdx.x >> 4;
    float4 acc[4];
#pragma unroll
    for (int i = 0; i < 4; ++i) acc[i] = make_float4(0.f, 0.f, 0.f, 0.f);
#pragma unroll 4
    for (int v = 0; v < NU; ++v) {
        float4 b = sW4[v * 16 + tx];
#pragma unroll
        for (int i = 0; i < 4; ++i) {
            float a = sX[(ty * 4 + i) * NU + v];
            acc[i].x = fmaf(a, b.x, acc[i].x);
            acc[i].y = fmaf(a, b.y, acc[i].y);
            acc[i].z = fmaf(a, b.z, acc[i].z);
            acc[i].w = fmaf(a, b.w, acc[i].w);
        }
    }
#pragma unroll
    for (int i = 0; i < 4; ++i)
        ((float4*)(dst + ((size_t)t * PT + n0 + ty * 4 + i) * NU))[half * 16 + tx] = acc[i];
}

// ============ k1b(t): raw = hist . qkx — quarter-warp rows, evict-first stream ============
__global__ void __launch_bounds__(128) k1b(const float* __restrict__ hist,
                                           const int* __restrict__ eidx, int t) {
    int lane = threadIdx.x & 31;
    int warp = threadIdx.x >> 5;
    int n = blockIdx.x * 4 + warp;
    int idx = eidx[t * PT + n];
    int g = lane >> 3;
    int c = lane & 7;

    const float4* qkrow = (const float4*)(g_QKX + ((size_t)t * PT + n) * NU);
    float4 qk[4];
#pragma unroll
    for (int j = 0; j < 4; ++j) qk[j] = __ldg(qkrow + j * 8 + c);

    const float* hb = hist + (size_t)idx * NH * NU;
    float* rawdst = g_RAW + ((size_t)t * PT + n) * NH;
#pragma unroll
    for (int i = 0; i < 8; ++i) {
        const float4* rowp = (const float4*)(hb + (4 * i + g) * NU);
        float4 v0 = __ldcs(rowp + 0 * 8 + c);
        float4 v1 = __ldcs(rowp + 1 * 8 + c);
        float4 v2 = __ldcs(rowp + 2 * 8 + c);
        float4 v3 = __ldcs(rowp + 3 * 8 + c);
        float p = 0.f;
        p = fmaf(v0.x, qk[0].x, p); p = fmaf(v0.y, qk[0].y, p);
        p = fmaf(v0.z, qk[0].z, p); p = fmaf(v0.w, qk[0].w, p);
        p = fmaf(v1.x, qk[1].x, p); p = fmaf(v1.y, qk[1].y, p);
        p = fmaf(v1.z, qk[1].z, p); p = fmaf(v1.w, qk[1].w, p);
        p = fmaf(v2.x, qk[2].x, p); p = fmaf(v2.y, qk[2].y, p);
        p = fmaf(v2.z, qk[2].z, p); p = fmaf(v2.w, qk[2].w, p);
        p = fmaf(v3.x, qk[3].x, p); p = fmaf(v3.y, qk[3].y, p);
        p = fmaf(v3.z, qk[3].z, p); p = fmaf(v3.w, qk[3].w, p);
        p += __shfl_xor_sync(0xffffffffu, p, 4);
        p += __shfl_xor_sync(0xffffffffu, p, 2);
        p += __shfl_xor_sync(0xffffffffu, p, 1);
        if (c == 0) rawdst[4 * i + g] = p;
    }
}

// ---------------- k2t(t): softmax stats for one type ----------------
__global__ void __launch_bounds__(256) k2t(int t) {
    int h = blockIdx.x;
    const float* base = g_RAW + (size_t)t * PT * NH + h;
    __shared__ float rm[256], rs[256];
    int tid = threadIdx.x;

    float m = -3.402823466e+38f, s = 0.f;
    for (int n = tid; n < PT; n += 256) {
        float x = base[(size_t)n * NH];
        if (x > m) { s = s * expf(m - x) + 1.f; m = x; }
        else s += expf(x - m);
    }
    rm[tid] = m; rs[tid] = s;
    __syncthreads();
#pragma unroll
    for (int st = 128; st; st >>= 1) {
        if (tid < st) {
            float m2 = rm[tid + st], s2 = rs[tid + st];
            float M = fmaxf(rm[tid], m2);
            rs[tid] = rs[tid] * expf(rm[tid] - M) + s2 * expf(m2 - M);
            rm[tid] = M;
        }
        __syncthreads();
    }
    if (tid == 0) { g_M[t * NH + h] = rm[0]; g_S[t * NH + h] = rs[0]; }
}

// ============ kout3(t): sparse-hbar + relu(hbar @ VF) + X @ qw  (g_HB eliminated) ============
// Sparse-hbar is bit-exact: fp32 softmax weights underflow to exactly 0.0 away from the
// per-(t,h) argmax (score gaps ~hundreds of sigma; expf underflows below -87). The fp32
// reference underflows identically, and fmaf(0, finite, acc) == acc, so skipping is exact.
__global__ void __launch_bounds__(256) kout3(const float* __restrict__ state,
                                             const float* __restrict__ hist,
                                             const int* __restrict__ eidx,
                                             const float* __restrict__ qw,
                                             float* __restrict__ out, int t) {
    extern __shared__ float smem[];
    float* sX = smem;                        // [64][128]
    float4* sW4 = (float4*)(smem + 64 * NU); // [128][16] float4
    int n0 = blockIdx.x * 64;
    int half = blockIdx.y;
    int lane = threadIdx.x & 31;
    int warp = threadIdx.x >> 5;             // 0..7
    int tx = threadIdx.x & 15;
    int ty = threadIdx.x >> 4;

    // ---- load VF half into sW4 ----
    {
        const float4* w4 = (const float4*)(g_VF + (size_t)t * NU * NU);
#pragma unroll
        for (int i = threadIdx.x; i < 2048; i += 256)
            sW4[i] = w4[(i >> 4) * 32 + half * 16 + (i & 15)];
    }

    // ---- sparse hbar into sX: each warp handles 8 entity rows ----
    {
        float Mv = g_M[t * NH + lane];
        float Sv = g_S[t * NH + lane];
#pragma unroll
        for (int j = 0; j < 8; ++j) {
            int r = warp * 8 + j;
            int n = n0 + r;
            int idx = eidx[t * PT + n];
            float raw = g_RAW[((size_t)t * PT + n) * NH + lane];
            float wv = expf(raw - Mv) / Sv;
            unsigned mask = __ballot_sync(0xffffffffu, wv != 0.0f);
            float4 hb = make_float4(0.f, 0.f, 0.f, 0.f);
            const float4* h4 = (const float4*)(hist + (size_t)idx * NH * NU);
            while (mask) {
                int h = __ffs(mask) - 1;
                mask &= mask - 1;
                float wh = __shfl_sync(0xffffffffu, wv, h);
                float4 r4 = __ldg(h4 + h * 32 + lane);
                hb.x = fmaf(wh, r4.x, hb.x); hb.y = fmaf(wh, r4.y, hb.y);
                hb.z = fmaf(wh, r4.z, hb.z); hb.w = fmaf(wh, r4.w, hb.w);
            }
            ((float4*)(sX + r * NU))[lane] = hb;
        }
    }
    __syncthreads();

    // ---- phase A GEMM: a1 = hbar @ VF ----
    float4 a1[4];
#pragma unroll
    for (int i = 0; i < 4; ++i) a1[i] = make_float4(0.f, 0.f, 0.f, 0.f);
#pragma unroll 4
    for (int v = 0; v < NU; ++v) {
        float4 b = sW4[v * 16 + tx];
#pragma unroll
        for (int i = 0; i < 4; ++i) {
            float a = sX[(ty * 4 + i) * NU + v];
            a1[i].x = fmaf(a, b.x, a1[i].x);
            a1[i].y = fmaf(a, b.y, a1[i].y);
            a1[i].z = fmaf(a, b.z, a1[i].z);
            a1[i].w = fmaf(a, b.w, a1[i].w);
        }
    }
    __syncthreads();

    // ---- phase B: gathered X @ qw ----
    {
        const float4* w4 = (const float4*)(qw + (size_t)t * NU * NU);
#pragma unroll
        for (int i = threadIdx.x; i < 2048; i += 256)
            sW4[i] = w4[(i >> 4) * 32 + half * 16 + (i & 15)];
        float4* sX4 = (float4*)sX;
#pragma unroll
        for (int i = threadIdx.x; i < 2048; i += 256) {
            int r = i >> 5, c = i & 31;
            int idx = eidx[t * PT + n0 + r];
            sX4[i] = __ldg((const float4*)(state + (size_t)idx * NU) + c);
        }
    }
    __syncthreads();

    float4 a2[4];
#pragma unroll
    for (int i = 0; i < 4; ++i) a2[i] = make_float4(0.f, 0.f, 0.f, 0.f);
#pragma unroll 4
    for (int v = 0; v < NU; ++v) {
        float4 b = sW4[v * 16 + tx];
#pragma unroll
        for (int i = 0; i < 4; ++i) {
            float a = sX[(ty * 4 + i) * NU + v];
            a2[i].x = fmaf(a, b.x, a2[i].x);
            a2[i].y = fmaf(a, b.y, a2[i].y);
            a2[i].z = fmaf(a, b.z, a2[i].z);
            a2[i].w = fmaf(a, b.w, a2[i].w);
        }
    }

#pragma unroll
    for (int i = 0; i < 4; ++i) {
        size_t row = (size_t)t * PT + n0 + ty * 4 + i;
        float4 r;
        r.x = fmaxf(a1[i].x, 0.f) + a2[i].x;
        r.y = fmaxf(a1[i].y, 0.f) + a2[i].y;
        r.z = fmaxf(a1[i].z, 0.f) + a2[i].z;
        r.w = fmaxf(a1[i].w, 0.f) + a2[i].w;
        ((float4*)(out + row * NU))[half * 16 + tx] = r;
    }
}

// ---------------- launch: k1b+stats chain, fully-fused epilogue ----------------
extern "C" void kernel_launch(void* const* d_in, const int* in_sizes, int n_in,
                              void* d_out, int out_size) {
    const float* state = (const float*)d_in[0];
    const float* hist  = (const float*)d_in[1];
    const int*   eidx  = (const int*)d_in[2];
    const float* qw    = (const float*)d_in[3];
    const float* kw    = (const float*)d_in[4];
    const float* vw    = (const float*)d_in[5];
    const float* fw    = (const float*)d_in[6];
    float* out = (float*)d_out;

    const int GSMEM = 64 * 1024;

    static bool init_done = false;
    static cudaStream_t s1, s2;
    static cudaEvent_t eP, gE[NT], hE[NT], e1, fE;
    static float* p_QKX;
    if (!init_done) {
        cudaFuncSetAttribute(kgemmH, cudaFuncAttributeMaxDynamicSharedMemorySize, GSMEM);
        cudaFuncSetAttribute(kout3, cudaFuncAttributeMaxDynamicSharedMemorySize, GSMEM);
        int lo, hi;
        cudaDeviceGetStreamPriorityRange(&lo, &hi);
        cudaStreamCreateWithPriority(&s1, cudaStreamNonBlocking, hi);
        cudaStreamCreateWithPriority(&s2, cudaStreamNonBlocking, lo);
        cudaEventCreateWithFlags(&eP, cudaEventDisableTiming);
        for (int t = 0; t < NT; ++t) {
            cudaEventCreateWithFlags(&gE[t], cudaEventDisableTiming);
            cudaEventCreateWithFlags(&hE[t], cudaEventDisableTiming);
        }
        cudaEventCreateWithFlags(&e1, cudaEventDisableTiming);
        cudaEventCreateWithFlags(&fE, cudaEventDisableTiming);
        cudaGetSymbolAddress((void**)&p_QKX, g_QKX);
        init_done = true;
    }

    // ---- s0: prep + per-type QKX GEMMs ----
    ktrans<<<dim3(4, 4, NT), dim3(32, 8)>>>(kw);
    kqk<<<dim3(NU, NT), NU>>>(qw);
    cudaEventRecord(eP, 0);
    for (int t = 0; t < NT; ++t) {
        kgemmH<<<dim3(PT / 64, 2), 256, GSMEM>>>(state, eidx, t, p_QKX);
        cudaEventRecord(gE[t], 0);
    }

    // ---- s1 (high prio): per-type chain k1b -> k2t (pass 2 now lives in kout3) ----
    for (int t = 0; t < NT; ++t) {
        cudaStreamWaitEvent(s1, gE[t], 0);
        k1b<<<PT / 4, 128, 0, s1>>>(hist, eidx, t);
        k2t<<<NH, 256, 0, s1>>>(t);
        cudaEventRecord(hE[t], s1);
    }
    cudaEventRecord(e1, s1);

    // ---- s2 (low prio): kvf hidden; fully-fused epilogue per type ----
    cudaStreamWaitEvent(s2, eP, 0);
    kvf<<<dim3(NU, NT), NU, 0, s2>>>(vw, fw);
    for (int t = 0; t < NT; ++t) {
        cudaStreamWaitEvent(s2, hE[t], 0);
        kout3<<<dim3(PT / 64, 2), 256, GSMEM, s2>>>(state, hist, eidx, qw, out, t);
    }
    cudaEventRecord(fE, s2);

    // ---- join ----
    cudaStreamWaitEvent(0, e1, 0);
    cudaStreamWaitEvent(0, fE, 0);
}